// round 4
// baseline (speedup 1.0000x reference)
#include <cuda_runtime.h>
#include <math_constants.h>

#define NB      256
#define LH      150
#define LQ      10
#define KITER   40
#define WWID    64
#define HW      4096
#define VW      66            // 64 + 2 halo cols
#define VSZ     (VW*VW)       // 4356
#define NTHREADS 512

typedef unsigned long long ull;

// smem float-offset layout
#define OFF_Q0    0                    // q0 quads: float4[(c2*64+row)*32+px] = 40960 floats
#define OFF_VA    40960                // v buffer A, halo'd (4356)
#define OFF_VB    (OFF_VA + VSZ)       // 45316  v buffer B, halo'd (4356)
#define OFF_SW4   (OFF_VB + VSZ)       // 49672  dup weights 10ch x 20 floats (16B aligned)
#define OFF_SWQ   (OFF_SW4 + 200)      // 49872  (Wq scalar, 90)
#define OFF_WEFF  (OFF_SWQ + 90)       // 49962  (18)
#define OFF_BEFF  (OFF_WEFF + 18)      // 49980  (1)
#define OFF_RED   (OFF_BEFF + 1)       // 49981  (16)
#define SMEM_FLOATS (OFF_RED + 16)     // 49997
#define SMEM_BYTES  (SMEM_FLOATS * 4)  // ~195.3 KB

__device__ __forceinline__ ull pk(float lo, float hi) {
    ull r; asm("mov.b64 %0, {%1, %2};" : "=l"(r) : "f"(lo), "f"(hi)); return r;
}
__device__ __forceinline__ void upk(ull p, float& lo, float& hi) {
    asm("mov.b64 {%0, %1}, %2;" : "=f"(lo), "=f"(hi) : "l"(p));
}
__device__ __forceinline__ ull fma2(ull a, ull b, ull c) {
    ull d; asm("fma.rn.f32x2 %0, %1, %2, %3;" : "=l"(d) : "l"(a), "l"(b), "l"(c)); return d;
}

// One value-iteration step, double-buffered (reads vcur, writes vnxt), one barrier.
// q_c = q0_c + conv3x3(v, w_c); v' = max_c q_c. If LAST, writes q to gmem instead.
template<bool LAST>
__device__ __forceinline__ void iter_body(
    const float* __restrict__ vcur, float* __restrict__ vnxt,
    const float* __restrict__ q0f, const float* __restrict__ sw4f,
    int y0, int x0, int px, float* __restrict__ qout_b,
    float vlo[4], float vhi[4])
{
    // window taps, rows y0..y0+5 (R2-proven pack construction)
    ull s0[6], s1[6], s2[6];
#pragma unroll
    for (int r = 0; r < 6; r++) {
        const float* row = vcur + (y0 + r) * VW + x0;   // 8B aligned (x0 even)
        ull p01 = *(const ull*)(row);
        ull p23 = *(const ull*)(row + 2);
        float u0, u1, u2, u3;
        upk(p01, u0, u1); upk(p23, u2, u3);
        s0[r] = p01;
        s1[r] = pk(u1, u2);
        s2[r] = p23;
    }
#pragma unroll
    for (int r = 0; r < 4; r++) { vlo[r] = -CUDART_INF_F; vhi[r] = -CUDART_INF_F; }

#pragma unroll
    for (int c2 = 0; c2 < 5; c2++) {
        // duplicated weight pairs for channels 2*c2, 2*c2+1 (broadcast vector loads)
        const ulonglong2* wA2 = (const ulonglong2*)(sw4f + c2 * 40);
        const ulonglong2* wB2 = (const ulonglong2*)(sw4f + c2 * 40 + 20);
        ulonglong2 a01 = wA2[0], a23 = wA2[1], a45 = wA2[2], a67 = wA2[3];
        ull a8 = ((const ull*)wA2)[8];
        ulonglong2 b01 = wB2[0], b23 = wB2[1], b45 = wB2[2], b67 = wB2[3];
        ull b8 = ((const ull*)wB2)[8];

        const ulonglong2* qrow = (const ulonglong2*)q0f + ((c2 * 64 + y0) * 32 + px);
#pragma unroll
        for (int r = 0; r < 4; r++) {
            ulonglong2 qq = qrow[r * 32];   // LDS.128: q0 for both channels
            ull accA = qq.x, accB = qq.y;
            accA = fma2(a01.x, s0[r    ], accA);
            accA = fma2(a01.y, s1[r    ], accA);
            accA = fma2(a23.x, s2[r    ], accA);
            accA = fma2(a23.y, s0[r + 1], accA);
            accA = fma2(a45.x, s1[r + 1], accA);
            accA = fma2(a45.y, s2[r + 1], accA);
            accA = fma2(a67.x, s0[r + 2], accA);
            accA = fma2(a67.y, s1[r + 2], accA);
            accA = fma2(a8,    s2[r + 2], accA);
            accB = fma2(b01.x, s0[r    ], accB);
            accB = fma2(b01.y, s1[r    ], accB);
            accB = fma2(b23.x, s2[r    ], accB);
            accB = fma2(b23.y, s0[r + 1], accB);
            accB = fma2(b45.x, s1[r + 1], accB);
            accB = fma2(b45.y, s2[r + 1], accB);
            accB = fma2(b67.x, s0[r + 2], accB);
            accB = fma2(b67.y, s1[r + 2], accB);
            accB = fma2(b8,    s2[r + 2], accB);
            float alo, ahi, blo, bhi;
            upk(accA, alo, ahi); upk(accB, blo, bhi);
            vlo[r] = fmaxf(fmaxf(vlo[r], alo), blo);
            vhi[r] = fmaxf(fmaxf(vhi[r], ahi), bhi);
            if (LAST) {
                *(ull*)(qout_b + (size_t)(2 * c2)     * HW + (y0 + r) * WWID + x0) = accA;
                *(ull*)(qout_b + (size_t)(2 * c2 + 1) * HW + (y0 + r) * WWID + x0) = accB;
            }
        }
    }
    if (!LAST) {
#pragma unroll
        for (int r = 0; r < 4; r++) {
            vnxt[(y0 + r + 1) * VW + x0 + 1] = vlo[r];
            vnxt[(y0 + r + 1) * VW + x0 + 2] = vhi[r];
        }
    }
    __syncthreads();
}

__global__ void __launch_bounds__(NTHREADS, 1)
vin_kernel(const float* __restrict__ X,  const float* __restrict__ Wh,
           const float* __restrict__ bh, const float* __restrict__ Wr,
           const float* __restrict__ Wq, const float* __restrict__ w,
           const float* __restrict__ Wc, const float* __restrict__ bc,
           float* __restrict__ out)
{
    extern __shared__ float smem[];
    float* q0f  = smem + OFF_Q0;
    float* vA   = smem + OFF_VA;
    float* vB   = smem + OFF_VB;
    float* sw4f = smem + OFF_SW4;
    float* sWq  = smem + OFF_SWQ;
    float* sweff= smem + OFF_WEFF;
    float* sbeff= smem + OFF_BEFF;
    float* sred = smem + OFF_RED;

    const int tid = threadIdx.x;
    const int b   = blockIdx.x;
    const int px  = tid & 31;      // pixel-pair index within row
    const int x0  = px << 1;       // left image column of the pair
    const int ty  = tid >> 5;      // 16 row-strips (== warp id)
    const int y0  = ty << 2;       // 4 image rows per thread

    // ---- stage 1: zero v buffers (halos stay 0), stage weights, Weff partials ----
    for (int i = tid; i < VSZ; i += NTHREADS) { vA[i] = 0.f; vB[i] = 0.f; }
    if (tid < 90) {
        const int c = tid / 9, t = tid % 9;
        const float wv = w[tid];
        sw4f[c * 20 + 2 * t]     = wv;
        sw4f[c * 20 + 2 * t + 1] = wv;
        sWq[tid] = Wq[tid];
    }
    {
        const int g = ty, k = px;   // 16 groups x first 19 lanes
        if (k < 19) {
            float s = 0.f;
            for (int lh = g; lh < LH; lh += 16) {
                const float wr = Wr[lh];
                s += wr * ((k < 18) ? Wh[lh * 18 + k] : bh[lh]);
            }
            q0f[g * 19 + k] = s;    // scratch in q0 region (dead before q0 writes)
        }
    }
    __syncthreads();

    // ---- stage 2: finalize Weff/beff; load X ch0 -> vA, ch1 -> vB ----
    if (tid < 19) {
        float s = 0.f;
#pragma unroll
        for (int g = 0; g < 16; g++) s += q0f[g * 19 + tid];
        if (tid < 18) sweff[tid] = s; else sbeff[0] = s;
    }
    const float* Xb = X + (size_t)b * 2 * HW;
    for (int i = tid; i < HW; i += NTHREADS) {
        const int yy = i >> 6, xx = i & 63;
        vA[(yy + 1) * VW + xx + 1] = Xb[i];
        vB[(yy + 1) * VW + xx + 1] = Xb[HW + i];
    }
    __syncthreads();

    // ---- stage 3: r = conv3x3([X0,X1], Weff) + beff (registers) ----
    float rr[4][2];
    {
        float wef[18];
#pragma unroll
        for (int i = 0; i < 18; i++) wef[i] = sweff[i];
        const float be = sbeff[0];
        float va[6][4], vb[6][4];
#pragma unroll
        for (int r = 0; r < 6; r++)
#pragma unroll
            for (int d = 0; d < 4; d++) {
                va[r][d] = vA[(y0 + r) * VW + x0 + d];
                vb[r][d] = vB[(y0 + r) * VW + x0 + d];
            }
#pragma unroll
        for (int r = 0; r < 4; r++)
#pragma unroll
            for (int d = 0; d < 2; d++) {
                float acc = be;
#pragma unroll
                for (int t = 0; t < 9; t++) {
                    const int ky = t / 3, kx = t % 3;
                    acc = fmaf(wef[t],     va[r + ky][d + kx], acc);
                    acc = fmaf(wef[9 + t], vb[r + ky][d + kx], acc);
                }
                rr[r][d] = acc;
            }
    }
    __syncthreads();   // all X reads done before overwriting vA with r
#pragma unroll
    for (int r = 0; r < 4; r++) {
        vA[(y0 + r + 1) * VW + x0 + 1] = rr[r][0];
        vA[(y0 + r + 1) * VW + x0 + 2] = rr[r][1];
    }
    __syncthreads();

    // ---- stage 4: q0 = conv3x3(r, Wq) -> quad smem; v0 = max_c q0 -> vB ----
    {
        float vr[6][4];
#pragma unroll
        for (int r = 0; r < 6; r++)
#pragma unroll
            for (int d = 0; d < 4; d++)
                vr[r][d] = vA[(y0 + r) * VW + x0 + d];
        float vm0[4], vm1[4];
#pragma unroll
        for (int r = 0; r < 4; r++) { vm0[r] = -CUDART_INF_F; vm1[r] = -CUDART_INF_F; }
#pragma unroll
        for (int c2 = 0; c2 < 5; c2++) {
            float wqa[9], wqb[9];
#pragma unroll
            for (int t = 0; t < 9; t++) {
                wqa[t] = sWq[(2 * c2) * 9 + t];
                wqb[t] = sWq[(2 * c2 + 1) * 9 + t];
            }
#pragma unroll
            for (int r = 0; r < 4; r++) {
                float a0 = 0.f, a1 = 0.f, b0 = 0.f, b1 = 0.f;
#pragma unroll
                for (int t = 0; t < 9; t++) {
                    const int ky = t / 3, kx = t % 3;
                    a0 = fmaf(wqa[t], vr[r + ky][kx],     a0);
                    a1 = fmaf(wqa[t], vr[r + ky][kx + 1], a1);
                    b0 = fmaf(wqb[t], vr[r + ky][kx],     b0);
                    b1 = fmaf(wqb[t], vr[r + ky][kx + 1], b1);
                }
                *(float4*)(q0f + ((c2 * 64 + y0 + r) * 32 + px) * 4) =
                    make_float4(a0, a1, b0, b1);
                vm0[r] = fmaxf(fmaxf(vm0[r], a0), b0);
                vm1[r] = fmaxf(fmaxf(vm1[r], a1), b1);
            }
        }
        // vB reads (stage 3) are two barriers old; safe to overwrite with v0
#pragma unroll
        for (int r = 0; r < 4; r++) {
            vB[(y0 + r + 1) * VW + x0 + 1] = vm0[r];
            vB[(y0 + r + 1) * VW + x0 + 2] = vm1[r];
        }
    }
    __syncthreads();

    // ---- stage 5: K=40 value-iteration steps, packed f32x2, double-buffered ----
    float* out_critic = out;
    float* out_q      = out + NB;
    float* qout_b     = out_q + (size_t)b * LQ * HW;
    float vlo[4], vhi[4];
    float* vcur = vB;
    float* vnxt = vA;   // r dead after stage 4; reuse (halo still 0)
#pragma unroll 1
    for (int k = 0; k < KITER - 1; k++) {
        iter_body<false>(vcur, vnxt, q0f, sw4f, y0, x0, px, qout_b, vlo, vhi);
        float* t = vcur; vcur = vnxt; vnxt = t;
    }
    iter_body<true>(vcur, vnxt, q0f, sw4f, y0, x0, px, qout_b, vlo, vhi);

    // ---- stage 6: critic = dot(v_final, Wc) + bc ----
    float part = 0.f;
#pragma unroll
    for (int r = 0; r < 4; r++) {
        part = fmaf(vlo[r], Wc[(y0 + r) * WWID + x0],     part);
        part = fmaf(vhi[r], Wc[(y0 + r) * WWID + x0 + 1], part);
    }
#pragma unroll
    for (int off = 16; off > 0; off >>= 1)
        part += __shfl_down_sync(0xffffffffu, part, off);
    if (px == 0) sred[ty] = part;
    __syncthreads();
    if (tid < 32) {
        float s = (tid < 16) ? sred[tid] : 0.f;
#pragma unroll
        for (int off = 8; off > 0; off >>= 1)
            s += __shfl_down_sync(0xffffffffu, s, off);
        if (tid == 0) out_critic[b] = s + bc[0];
    }
}

extern "C" void kernel_launch(void* const* d_in, const int* in_sizes, int n_in,
                              void* d_out, int out_size) {
    const float* X  = (const float*)d_in[0];
    const float* Wh = (const float*)d_in[1];
    const float* bh = (const float*)d_in[2];
    const float* Wr = (const float*)d_in[3];
    const float* Wq = (const float*)d_in[4];
    const float* w  = (const float*)d_in[5];
    const float* Wc = (const float*)d_in[6];
    const float* bc = (const float*)d_in[7];
    float* out = (float*)d_out;

    cudaFuncSetAttribute(vin_kernel, cudaFuncAttributeMaxDynamicSharedMemorySize,
                         SMEM_BYTES);
    vin_kernel<<<NB, NTHREADS, SMEM_BYTES>>>(X, Wh, bh, Wr, Wq, w, Wc, bc, out);
}